// round 10
// baseline (speedup 1.0000x reference)
#include <cuda_runtime.h>
#include <math.h>

#define NBOX   4096
#define RPB    128                      // pred rows per pair block
#define CHUNK  128                      // targets per pair block
#define NBLK   1024                     // 32x32 pair blocks
#define NCELL  64                       // 8x8 spatial cells (100px), morton order

// Scratch (device globals: no allocation allowed in kernel_launch)
__device__ int    g_cnt[2 * NCELL];     // per-side per-cell counts (zeroed by final)
__device__ float4 g_sP4[NBOX];          // spatially sorted preds
__device__ int    g_sPi[NBOX];          // original indices
__device__ float4 g_sT4[NBOX];          // spatially sorted targets
__device__ int    g_sTi[NBOX];
__device__ float4 g_pbb[32];            // pred-chunk bbox (mnx0, mxx2, mny0, mxy2) raw
__device__ float4 g_tbb[32];            // tgt-chunk bbox
__device__ unsigned long long g_best[NBOX]; // packed (ratio_bits<<32 | ~argOrig); 0 = none
__device__ float  g_rbS[NBLK];
__device__ int    g_rbC[NBLK];
__device__ double g_pG[32];             // per-bx RepGT sln partials
__device__ int    g_pC[32];             // per-bx RepGT counts
__device__ double g_pL[4];              // smooth-L1 partials (sort blocks 4-7)
__device__ unsigned int g_syncA, g_syncB;   // sort grid barriers (zeroed by final)
__device__ unsigned int g_bxT[32];          // per-bx pair tickets (zeroed by final)

__device__ __forceinline__ int cellOf(float x, float y) {
    int cx = (int)(x * 0.01f); cx = cx < 0 ? 0 : (cx > 7 ? 7 : cx);
    int cy = (int)(y * 0.01f); cy = cy < 0 ? 0 : (cy > 7 ? 7 : cy);
    return (cx & 1) | ((cy & 1) << 1) | ((cx & 2) << 1) |
           ((cy & 2) << 2) | ((cx & 4) << 2) | ((cy & 4) << 3);
}

// ---------------------------------------------------------------------------
// Kernel 0: fused rank + scatter + sl1 partial + chunk bboxes.
// 8 blocks x 1024 (all co-resident -> spin grid barriers are safe).
// blocks 0-3: targets, 4-7: preds.
// ---------------------------------------------------------------------------
__global__ __launch_bounds__(1024)
void sort_kernel(const float4* __restrict__ pred4,
                 const float4* __restrict__ tgt4)
{
    const int tid  = threadIdx.x;
    const int side = blockIdx.x >> 2;               // 0 = tgt, 1 = pred
    const int idx  = (blockIdx.x & 3) * 1024 + tid;
    const float4* src = side ? pred4 : tgt4;
    float4* dst  = side ? g_sP4 : g_sT4;
    int*    dsti = side ? g_sPi : g_sTi;
    const int lane = tid & 31, wrp = tid >> 5;

    __shared__ int sh[NCELL], sbase[NCELL], soff[NCELL];
    if (tid < NCELL) sh[tid] = 0;
    __syncthreads();

    const float4 v = src[idx];
    const int cell = cellOf(v.x, v.y);
    const int lr   = atomicAdd(&sh[cell], 1);
    __syncthreads();
    if (tid < NCELL) sbase[tid] = atomicAdd(&g_cnt[side * NCELL + tid], sh[tid]);
    __syncthreads();
    const int rank = sbase[cell] + lr;

    // smooth-L1 partial (pred-side blocks): elements [4*idx, 4*idx+4)
    if (side) {
        const float4 tv = tgt4[idx];
        float slf = 0.0f, d;
        d = fabsf(v.x - tv.x); slf += (d < 1.0f) ? 0.5f * d * d : d - 0.5f;
        d = fabsf(v.y - tv.y); slf += (d < 1.0f) ? 0.5f * d * d : d - 0.5f;
        d = fabsf(v.z - tv.z); slf += (d < 1.0f) ? 0.5f * d * d : d - 0.5f;
        d = fabsf(v.w - tv.w); slf += (d < 1.0f) ? 0.5f * d * d : d - 0.5f;
        double sl = (double)slf;
        #pragma unroll
        for (int o = 16; o > 0; o >>= 1) sl += __shfl_down_sync(0xffffffffu, sl, o);
        __shared__ double sWL[32];
        if (lane == 0) sWL[wrp] = sl;
        __syncthreads();
        if (tid == 0) {
            double a = 0.0;
            #pragma unroll
            for (int w = 0; w < 32; ++w) a += sWL[w];
            g_pL[blockIdx.x - 4] = a;
        }
    }

    // ---- grid barrier A: all counts final ----
    if (tid == 0) {
        __threadfence();
        atomicAdd(&g_syncA, 1u);
        while (atomicAdd(&g_syncA, 0u) < 8u) {}
    }
    __syncthreads();

    if (tid == 0) {
        int acc = 0;
        for (int c = 0; c < NCELL; ++c) { soff[c] = acc; acc += g_cnt[side * NCELL + c]; }
    }
    __syncthreads();
    const int pos = soff[cell] + rank;
    dst[pos]  = v;
    dsti[pos] = idx;

    // ---- grid barrier B: sorted arrays complete ----
    if (tid == 0) {
        __threadfence();
        atomicAdd(&g_syncB, 1u);
        while (atomicAdd(&g_syncB, 0u) < 8u) {}
    }
    __syncthreads();

    // chunk bboxes: block 0 -> tgt, block 4 -> pred (warp w owns chunk w)
    if (blockIdx.x == 0 || blockIdx.x == 4) {
        const float4* d = side ? g_sP4 : g_sT4;
        float4* bb = side ? g_pbb : g_tbb;
        float mnx = 1e30f, mxx = -1e30f, mny = 1e30f, mxy = -1e30f;
        #pragma unroll
        for (int q = 0; q < 4; ++q) {
            const float4 bx4 = d[wrp * 128 + q * 32 + lane];
            mnx = fminf(mnx, bx4.x); mxx = fmaxf(mxx, bx4.z);
            mny = fminf(mny, bx4.y); mxy = fmaxf(mxy, bx4.w);
        }
        #pragma unroll
        for (int o = 16; o > 0; o >>= 1) {
            mnx = fminf(mnx, __shfl_xor_sync(0xffffffffu, mnx, o));
            mxx = fmaxf(mxx, __shfl_xor_sync(0xffffffffu, mxx, o));
            mny = fminf(mny, __shfl_xor_sync(0xffffffffu, mny, o));
            mxy = fmaxf(mxy, __shfl_xor_sync(0xffffffffu, mxy, o));
        }
        if (lane == 0) bb[wrp] = make_float4(mnx, mxx, mny, mxy);
    }
}

// ---------------------------------------------------------------------------
// Kernel 1: culled pair sweep + distributed RepGT finalize.
// Block cull via precomputed chunk bboxes (before any tile load). Target
// compaction vs pred-chunk bbox. Last block per bx (ticket) finalizes the
// 128 rows of its pred chunk: reads final g_best, computes IoG + smooth_ln.
// ---------------------------------------------------------------------------
__global__ __launch_bounds__(RPB)
void pair_kernel(const float4* __restrict__ pred4,
                 const float4* __restrict__ tgt4)
{
    const int tid = threadIdx.x;
    const int bx = blockIdx.x, by = blockIdx.y;
    const int b  = bx * 32 + by;
    const int lane = tid & 31, wrp = tid >> 5;

    __shared__ float4 sT2[CHUNK];
    __shared__ float2 sAJ2[CHUNK];
    __shared__ int sCnt[4], sBase[4], sN;
    __shared__ unsigned int sLast;

    const float4 pb = g_pbb[bx];        // (mnx, mxx_raw, mny, mxy_raw)
    const float4 tb = g_tbb[by];
    const bool hit = (pb.y + 1.0f > tb.x) && (tb.y + 1.0f > pb.x) &&
                     (pb.w + 1.0f > tb.z) && (tb.w + 1.0f > pb.z);

    if (hit) {
        // my pred row
        const int r = bx * RPB + tid;
        float4 p = g_sP4[r];
        const int iO = g_sPi[r];
        const float areaP = (p.z - p.x + 1.0f) * (p.w - p.y + 1.0f);
        p.z += 1.0f; p.w += 1.0f;

        // my target: test vs pred-chunk bbox, deterministic compaction
        {
            float4 t = g_sT4[by * CHUNK + tid];
            const int jO = g_sTi[by * CHUNK + tid];
            const float a = (t.z - t.x + 1.0f) * (t.w - t.y + 1.0f);
            t.z += 1.0f; t.w += 1.0f;
            const bool pass = (pb.y + 1.0f > t.x) && (t.z > pb.x) &&
                              (pb.w + 1.0f > t.y) && (t.w > pb.z);
            const unsigned m = __ballot_sync(0xffffffffu, pass);
            if (lane == 0) sCnt[wrp] = __popc(m);
            __syncthreads();
            if (tid == 0) {
                int acc = 0;
                #pragma unroll
                for (int w = 0; w < 4; ++w) { sBase[w] = acc; acc += sCnt[w]; }
                sN = acc;
            }
            __syncthreads();
            if (pass) {
                const int pos = sBase[wrp] + __popc(m & ((1u << lane) - 1u));
                sT2[pos]  = t;
                sAJ2[pos] = make_float2(a, __int_as_float(jO));
            }
        }
        __syncthreads();

        const int nAct = sN;
        float bI = 0.0f, bU = 1.0f;
        int   bA = 0;
        float rbS = 0.0f;
        int   rbC = 0;

        #pragma unroll 4
        for (int k = 0; k < nAct; ++k) {
            const float4 t  = sT2[k];
            const float2 aj = sAJ2[k];
            float iw = fminf(p.z, t.z) - fmaxf(p.x, t.x);
            float ih = fminf(p.w, t.w) - fmaxf(p.y, t.y);
            iw = fmaxf(iw, 0.0f);
            ih = fmaxf(ih, 0.0f);
            const float inter = iw * ih;
            const float ua    = areaP + aj.x - inter;
            const int   jO    = __float_as_int(aj.y);
            if ((jO != iO) && (inter * bU > bI * ua)) {
                bI = inter; bU = ua; bA = jO;
            }
            if ((jO < iO) && (inter > 0.0f)) {
                rbS += __fdividef(inter, ua);
                rbC += 1;
            }
        }

        if (bI > 0.0f) {
            const float ratio = bI / bU;
            const unsigned long long packed =
                ((unsigned long long)__float_as_uint(ratio) << 32) |
                (unsigned long long)(0xFFFFFFFFu - (unsigned)bA);
            atomicMax(&g_best[iO], packed);
        }

        #pragma unroll
        for (int o = 16; o > 0; o >>= 1) {
            rbS += __shfl_down_sync(0xffffffffu, rbS, o);
            rbC += __shfl_down_sync(0xffffffffu, rbC, o);
        }
        __shared__ float wS[4];
        __shared__ int   wC[4];
        if (lane == 0) { wS[wrp] = rbS; wC[wrp] = rbC; }
        __syncthreads();
        if (tid == 0) {
            float s = 0.0f; int c = 0;
            #pragma unroll
            for (int w = 0; w < 4; ++w) { s += wS[w]; c += wC[w]; }
            g_rbS[b] = s;
            g_rbC[b] = c;
        }
    } else {
        if (tid == 0) { g_rbS[b] = 0.0f; g_rbC[b] = 0; }
    }

    // ---- per-bx ticket; last block finalizes this pred chunk's 128 rows ----
    __syncthreads();
    if (tid == 0) {
        __threadfence();
        sLast = (atomicAdd(&g_bxT[bx], 1u) == 31u) ? 1u : 0u;
    }
    __syncthreads();
    if (sLast == 0u) return;

    {
        const int r2  = bx * RPB + tid;
        const int iO2 = g_sPi[r2];
        const unsigned long long packed = __ldcg(&g_best[iO2]);
        g_best[iO2] = 0ull;                 // reset for next replay

        float sgf = 0.0f;
        int   cgi = 0;
        if (packed != 0ull) {
            const int bA2 = (int)(0xFFFFFFFFu - (unsigned)(packed & 0xFFFFFFFFull));
            const float4 pe = pred4[iO2];
            const float4 g  = tgt4[bA2];
            const float iw = fmaxf(fminf(pe.z, g.z) - fmaxf(pe.x, g.x), 0.0f);
            const float ih = fmaxf(fminf(pe.w, g.w) - fmaxf(pe.y, g.y), 0.0f);
            const float garea = (g.z - g.x) * (g.w - g.y);
            const float iog = iw * ih / garea;      // no +1 convention for IoG
            if (iog > 0.9f) {
                sgf = (iog - 0.9f) / (1.0f - 0.9f) + 2.3025851f;  // -log1p(-0.9)
            } else {
                const float xc = fminf(fmaxf(iog, 0.0f), 1.0f - 1e-6f);
                sgf = -log1pf(-xc);
            }
            cgi = 1;
        }

        double sg = (double)sgf;
        int cg = cgi;
        #pragma unroll
        for (int o = 16; o > 0; o >>= 1) {
            sg += __shfl_down_sync(0xffffffffu, sg, o);
            cg += __shfl_down_sync(0xffffffffu, cg, o);
        }
        __shared__ double fG[4];
        __shared__ int    fC[4];
        if (lane == 0) { fG[wrp] = sg; fC[wrp] = cg; }
        __syncthreads();
        if (tid == 0) {
            double tg = 0.0; int tc = 0;
            #pragma unroll
            for (int w = 0; w < 4; ++w) { tg += fG[w]; tc += fC[w]; }
            g_pG[bx] = tg;
            g_pC[bx] = tc;
        }
    }
}

// ---------------------------------------------------------------------------
// Kernel 2: final reduce + broadcast + scratch reset. 1 block x 1024.
// ---------------------------------------------------------------------------
__global__ __launch_bounds__(1024)
void final_kernel(float* __restrict__ out)
{
    const int tid = threadIdx.x;
    const int lane = tid & 31, wrp = tid >> 5;

    double trb = (double)__ldcg(&g_rbS[tid]);       // NBLK == 1024 == blockDim
    long long tcb = (long long)__ldcg(&g_rbC[tid]);
    double tsg = 0.0, tsl = 0.0;
    int tcg = 0;
    if (tid < 32) { tsg = __ldcg(&g_pG[tid]); tcg = __ldcg(&g_pC[tid]); }
    if (tid < 4)  { tsl = __ldcg(&g_pL[tid]); }

    // reset scratch for next graph replay (g_best reset by pair finalize)
    if (tid < 2 * NCELL) g_cnt[tid] = 0;
    if (tid < 32) g_bxT[tid] = 0u;
    if (tid == 0) { g_syncA = 0u; g_syncB = 0u; }

    #pragma unroll
    for (int o = 16; o > 0; o >>= 1) {
        trb += __shfl_down_sync(0xffffffffu, trb, o);
        tcb += __shfl_down_sync(0xffffffffu, tcb, o);
        tsg += __shfl_down_sync(0xffffffffu, tsg, o);
        tsl += __shfl_down_sync(0xffffffffu, tsl, o);
        tcg += __shfl_down_sync(0xffffffffu, tcg, o);
    }
    __shared__ double sR[32], sG[32], sL[32];
    __shared__ long long sB[32];
    __shared__ int sC[32];
    __shared__ float sScalar;
    if (lane == 0) { sR[wrp] = trb; sB[wrp] = tcb; sG[wrp] = tsg;
                     sL[wrp] = tsl; sC[wrp] = tcg; }
    __syncthreads();
    if (tid == 0) {
        double ar = 0.0, ag = 0.0, al = 0.0;
        long long ab = 0; int ac = 0;
        #pragma unroll
        for (int w = 0; w < 32; ++w) {
            ar += sR[w]; ab += sB[w]; ag += sG[w]; al += sL[w]; ac += sC[w];
        }
        const float sl1    = (float)(al / (double)(NBOX * 4));
        const float repgt  = (ac > 0) ? (float)(ag / (double)ac) : 0.0f;
        const float repbox = (ab > 0) ? (float)(ar / (double)ab) : 0.0f;
        sScalar = sl1 + repgt + repbox;
    }
    __syncthreads();

    const float s = sScalar;
    float4* out4 = (float4*)out;
    out4[tid] = make_float4(s, s, s, s);            // 1024 float4 == 4096 floats
}

// ---------------------------------------------------------------------------
extern "C" void kernel_launch(void* const* d_in, const int* in_sizes, int n_in,
                              void* d_out, int out_size)
{
    const float* pred = (const float*)d_in[0];
    const float* tgt  = (const float*)d_in[1];
    float* out = (float*)d_out;

    sort_kernel<<<8, 1024>>>((const float4*)pred, (const float4*)tgt);
    dim3 grid(32, 32);
    pair_kernel<<<grid, RPB>>>((const float4*)pred, (const float4*)tgt);
    final_kernel<<<1, 1024>>>(out);
}

// round 11
// speedup vs baseline: 1.1044x; 1.1044x over previous
#include <cuda_runtime.h>
#include <math.h>

#define NBOX   4096
#define RPB    128                      // pred rows per pair block
#define CHUNK  128                      // targets per pair block
#define NBLK   1024                     // 32x32 pair blocks
#define NCELL  64                       // 8x8 spatial cells (100px), morton order

// Scratch (device globals: no allocation allowed in kernel_launch)
__device__ int    g_cnt[2 * NCELL];     // per-side per-cell counts (zeroed by final)
__device__ int    g_cr[2 * NBOX];       // packed (cell<<12 | rank) per element
__device__ float4 g_sP4[NBOX];          // spatially sorted preds
__device__ int    g_sPi[NBOX];          // original indices
__device__ float4 g_sT4[NBOX];          // spatially sorted targets
__device__ int    g_sTi[NBOX];
__device__ unsigned long long g_best[NBOX]; // packed (ratio_bits<<32 | ~argOrig); 0 = none
__device__ float  g_rbS[NBLK];
__device__ int    g_rbC[NBLK];
__device__ double g_pG[32];             // per-bx RepGT sln partials
__device__ int    g_pC[32];             // per-bx RepGT counts
__device__ double g_pL[4];              // smooth-L1 partials (rank blocks 4-7)
__device__ unsigned int g_bxT[32];      // per-bx pair tickets (zeroed by final)

__device__ __forceinline__ int cellOf(float x, float y) {
    int cx = (int)(x * 0.01f); cx = cx < 0 ? 0 : (cx > 7 ? 7 : cx);
    int cy = (int)(y * 0.01f); cy = cy < 0 ? 0 : (cy > 7 ? 7 : cy);
    return (cx & 1) | ((cy & 1) << 1) | ((cx & 2) << 1) |
           ((cy & 2) << 2) | ((cx & 4) << 2) | ((cy & 4) << 3);
}

// ---------------------------------------------------------------------------
// Kernel 0a: rank. 8 blocks x 1024 = one thread per element.
// blocks 0-3: targets, 4-7: preds (pred blocks also emit sl1 partials).
// ---------------------------------------------------------------------------
__global__ __launch_bounds__(1024)
void rank_kernel(const float4* __restrict__ pred4,
                 const float4* __restrict__ tgt4)
{
    const int tid  = threadIdx.x;
    const int side = blockIdx.x >> 2;               // 0 = tgt, 1 = pred
    const int idx  = (blockIdx.x & 3) * 1024 + tid;
    const float4* src = side ? pred4 : tgt4;
    const int lane = tid & 31, wrp = tid >> 5;

    __shared__ int sh[NCELL];
    __shared__ int sbase[NCELL];
    if (tid < NCELL) sh[tid] = 0;
    __syncthreads();

    const float4 v = src[idx];
    const int cell = cellOf(v.x, v.y);
    const int lr   = atomicAdd(&sh[cell], 1);
    __syncthreads();
    if (tid < NCELL) sbase[tid] = atomicAdd(&g_cnt[side * NCELL + tid], sh[tid]);
    __syncthreads();

    g_cr[side * NBOX + idx] = (cell << 12) | (sbase[cell] + lr);

    // smooth-L1 partial on pred-side blocks: elements [4*idx, 4*idx+4)
    if (side) {
        const float4 tv = tgt4[idx];
        float slf = 0.0f, d;
        d = fabsf(v.x - tv.x); slf += (d < 1.0f) ? 0.5f * d * d : d - 0.5f;
        d = fabsf(v.y - tv.y); slf += (d < 1.0f) ? 0.5f * d * d : d - 0.5f;
        d = fabsf(v.z - tv.z); slf += (d < 1.0f) ? 0.5f * d * d : d - 0.5f;
        d = fabsf(v.w - tv.w); slf += (d < 1.0f) ? 0.5f * d * d : d - 0.5f;
        double sl = (double)slf;
        #pragma unroll
        for (int o = 16; o > 0; o >>= 1) sl += __shfl_down_sync(0xffffffffu, sl, o);
        __shared__ double sWL[32];
        if (lane == 0) sWL[wrp] = sl;
        __syncthreads();
        if (tid == 0) {
            double a = 0.0;
            #pragma unroll
            for (int w = 0; w < 32; ++w) a += sWL[w];
            g_pL[blockIdx.x - 4] = a;
        }
    }
}

// ---------------------------------------------------------------------------
// Kernel 0b: scatter. 8 blocks x 1024.
// ---------------------------------------------------------------------------
__global__ __launch_bounds__(1024)
void scatter_kernel(const float4* __restrict__ pred4,
                    const float4* __restrict__ tgt4)
{
    const int tid  = threadIdx.x;
    const int side = blockIdx.x >> 2;
    const int idx  = (blockIdx.x & 3) * 1024 + tid;
    const float4* src = side ? pred4 : tgt4;
    float4* dst  = side ? g_sP4 : g_sT4;
    int*    dsti = side ? g_sPi : g_sTi;

    __shared__ int soff[NCELL];
    if (tid == 0) {
        int acc = 0;
        for (int c = 0; c < NCELL; ++c) { soff[c] = acc; acc += g_cnt[side * NCELL + c]; }
    }
    __syncthreads();

    const int cr   = g_cr[side * NBOX + idx];
    const int pos  = soff[cr >> 12] + (cr & 0xFFF);
    dst[pos]  = src[idx];
    dsti[pos] = idx;
}

// ---------------------------------------------------------------------------
// Kernel 1: pair sweep with block-level target compaction + distributed
// RepGT finalize (last block per bx finalizes its pred chunk's 128 rows).
// ---------------------------------------------------------------------------
__global__ __launch_bounds__(RPB)
void pair_kernel(const float4* __restrict__ pred4,
                 const float4* __restrict__ tgt4)
{
    const int tid = threadIdx.x;
    const int bx = blockIdx.x, by = blockIdx.y;
    const int b  = bx * 32 + by;
    const int lane = tid & 31, wrp = tid >> 5;

    __shared__ float4 sT2[CHUNK];   // compacted targets {x0, y0, x2+1, y2+1}
    __shared__ float2 sAJ2[CHUNK];  // compacted (area+1conv, orig idx bits)
    __shared__ float4 sPB[4];       // per-warp pred bbox
    __shared__ int sCnt[4], sBase[4], sN;
    __shared__ unsigned int sLast;

    // --- own pred row + warp bbox ---
    const int r = bx * RPB + tid;
    float4 p = g_sP4[r];
    const int iO = g_sPi[r];
    const float areaP = (p.z - p.x + 1.0f) * (p.w - p.y + 1.0f);
    p.z += 1.0f; p.w += 1.0f;

    {
        float mnx = p.x, mxx = p.z, mny = p.y, mxy = p.w;
        #pragma unroll
        for (int o = 16; o > 0; o >>= 1) {
            mnx = fminf(mnx, __shfl_xor_sync(0xffffffffu, mnx, o));
            mxx = fmaxf(mxx, __shfl_xor_sync(0xffffffffu, mxx, o));
            mny = fminf(mny, __shfl_xor_sync(0xffffffffu, mny, o));
            mxy = fmaxf(mxy, __shfl_xor_sync(0xffffffffu, mxy, o));
        }
        if (lane == 0) sPB[wrp] = make_float4(mnx, mxx, mny, mxy);
    }
    __syncthreads();

    // block pred bbox (uniform)
    const float pmnx = fminf(fminf(sPB[0].x, sPB[1].x), fminf(sPB[2].x, sPB[3].x));
    const float pmxx = fmaxf(fmaxf(sPB[0].y, sPB[1].y), fmaxf(sPB[2].y, sPB[3].y));
    const float pmny = fminf(fminf(sPB[0].z, sPB[1].z), fminf(sPB[2].z, sPB[3].z));
    const float pmxy = fmaxf(fmaxf(sPB[0].w, sPB[1].w), fmaxf(sPB[2].w, sPB[3].w));

    // --- load my target, test vs block bbox, deterministic compaction ---
    {
        float4 t = g_sT4[by * CHUNK + tid];
        const int jO = g_sTi[by * CHUNK + tid];
        const float a = (t.z - t.x + 1.0f) * (t.w - t.y + 1.0f);
        t.z += 1.0f; t.w += 1.0f;
        const bool pass = (pmxx > t.x) && (t.z > pmnx) &&
                          (pmxy > t.y) && (t.w > pmny);
        const unsigned m = __ballot_sync(0xffffffffu, pass);
        if (lane == 0) sCnt[wrp] = __popc(m);
        __syncthreads();
        if (tid == 0) {
            int acc = 0;
            #pragma unroll
            for (int w = 0; w < 4; ++w) { sBase[w] = acc; acc += sCnt[w]; }
            sN = acc;
        }
        __syncthreads();
        if (pass) {
            const int pos = sBase[wrp] + __popc(m & ((1u << lane) - 1u));
            sT2[pos]  = t;
            sAJ2[pos] = make_float2(a, __int_as_float(jO));
        }
    }
    __syncthreads();

    const int nAct = sN;
    {
        float bI = 0.0f, bU = 1.0f;
        int   bA = 0;
        float rbS = 0.0f;
        int   rbC = 0;

        #pragma unroll 4
        for (int k = 0; k < nAct; ++k) {
            const float4 t  = sT2[k];
            const float2 aj = sAJ2[k];
            float iw = fminf(p.z, t.z) - fmaxf(p.x, t.x);
            float ih = fminf(p.w, t.w) - fmaxf(p.y, t.y);
            iw = fmaxf(iw, 0.0f);
            ih = fmaxf(ih, 0.0f);
            const float inter = iw * ih;
            const float ua    = areaP + aj.x - inter;
            const int   jO    = __float_as_int(aj.y);
            if ((jO != iO) && (inter * bU > bI * ua)) {
                bI = inter; bU = ua; bA = jO;
            }
            if ((jO < iO) && (inter > 0.0f)) {
                rbS += __fdividef(inter, ua);
                rbC += 1;
            }
        }

        if (bI > 0.0f) {
            const float ratio = bI / bU;
            const unsigned long long packed =
                ((unsigned long long)__float_as_uint(ratio) << 32) |
                (unsigned long long)(0xFFFFFFFFu - (unsigned)bA);
            atomicMax(&g_best[iO], packed);    // indexed by ORIGINAL row
        }

        #pragma unroll
        for (int o = 16; o > 0; o >>= 1) {
            rbS += __shfl_down_sync(0xffffffffu, rbS, o);
            rbC += __shfl_down_sync(0xffffffffu, rbC, o);
        }
        __shared__ float wS[4];
        __shared__ int   wC[4];
        if (lane == 0) { wS[wrp] = rbS; wC[wrp] = rbC; }
        __syncthreads();
        if (tid == 0) {
            float s = 0.0f; int c = 0;
            #pragma unroll
            for (int w = 0; w < 4; ++w) { s += wS[w]; c += wC[w]; }
            g_rbS[b] = s;
            g_rbC[b] = c;
        }
    }

    // ---- per-bx ticket; last block finalizes this pred chunk's 128 rows ----
    __syncthreads();
    if (tid == 0) {
        __threadfence();
        sLast = (atomicAdd(&g_bxT[bx], 1u) == 31u) ? 1u : 0u;
    }
    __syncthreads();
    if (sLast == 0u) return;

    {
        const unsigned long long packed = __ldcg(&g_best[iO]);
        g_best[iO] = 0ull;                  // reset for next replay

        float sgf = 0.0f;
        int   cgi = 0;
        if (packed != 0ull) {               // max_ov > 0 mask
            const int bA2 = (int)(0xFFFFFFFFu - (unsigned)(packed & 0xFFFFFFFFull));
            const float4 pe = pred4[iO];
            const float4 g  = tgt4[bA2];
            const float iw = fmaxf(fminf(pe.z, g.z) - fmaxf(pe.x, g.x), 0.0f);
            const float ih = fmaxf(fminf(pe.w, g.w) - fmaxf(pe.y, g.y), 0.0f);
            const float garea = (g.z - g.x) * (g.w - g.y);
            const float iog = iw * ih / garea;      // no +1 convention for IoG
            if (iog > 0.9f) {
                sgf = (iog - 0.9f) / (1.0f - 0.9f) + 2.3025851f;  // -log1p(-0.9)
            } else {
                const float xc = fminf(fmaxf(iog, 0.0f), 1.0f - 1e-6f);
                sgf = -log1pf(-xc);
            }
            cgi = 1;
        }

        double sg = (double)sgf;
        int cg = cgi;
        #pragma unroll
        for (int o = 16; o > 0; o >>= 1) {
            sg += __shfl_down_sync(0xffffffffu, sg, o);
            cg += __shfl_down_sync(0xffffffffu, cg, o);
        }
        __shared__ double fG[4];
        __shared__ int    fC[4];
        if (lane == 0) { fG[wrp] = sg; fC[wrp] = cg; }
        __syncthreads();
        if (tid == 0) {
            double tg = 0.0; int tc = 0;
            #pragma unroll
            for (int w = 0; w < 4; ++w) { tg += fG[w]; tc += fC[w]; }
            g_pG[bx] = tg;
            g_pC[bx] = tc;
        }
    }
}

// ---------------------------------------------------------------------------
// Kernel 2: final reduce + broadcast + scratch reset. 1 block x 1024.
// ---------------------------------------------------------------------------
__global__ __launch_bounds__(1024)
void final_kernel(float* __restrict__ out)
{
    const int tid = threadIdx.x;
    const int lane = tid & 31, wrp = tid >> 5;

    double trb = (double)__ldcg(&g_rbS[tid]);       // NBLK == 1024 == blockDim
    long long tcb = (long long)__ldcg(&g_rbC[tid]);
    double tsg = 0.0, tsl = 0.0;
    int tcg = 0;
    if (tid < 32) { tsg = __ldcg(&g_pG[tid]); tcg = __ldcg(&g_pC[tid]); }
    if (tid < 4)  { tsl = __ldcg(&g_pL[tid]); }

    // reset scratch for next graph replay (g_best reset by pair finalize)
    if (tid < 2 * NCELL) g_cnt[tid] = 0;
    if (tid < 32) g_bxT[tid] = 0u;

    #pragma unroll
    for (int o = 16; o > 0; o >>= 1) {
        trb += __shfl_down_sync(0xffffffffu, trb, o);
        tcb += __shfl_down_sync(0xffffffffu, tcb, o);
        tsg += __shfl_down_sync(0xffffffffu, tsg, o);
        tsl += __shfl_down_sync(0xffffffffu, tsl, o);
        tcg += __shfl_down_sync(0xffffffffu, tcg, o);
    }
    __shared__ double sR[32], sG[32], sL[32];
    __shared__ long long sB[32];
    __shared__ int sC[32];
    __shared__ float sScalar;
    if (lane == 0) { sR[wrp] = trb; sB[wrp] = tcb; sG[wrp] = tsg;
                     sL[wrp] = tsl; sC[wrp] = tcg; }
    __syncthreads();
    if (tid == 0) {
        double ar = 0.0, ag = 0.0, al = 0.0;
        long long ab = 0; int ac = 0;
        #pragma unroll
        for (int w = 0; w < 32; ++w) {
            ar += sR[w]; ab += sB[w]; ag += sG[w]; al += sL[w]; ac += sC[w];
        }
        const float sl1    = (float)(al / (double)(NBOX * 4));
        const float repgt  = (ac > 0) ? (float)(ag / (double)ac) : 0.0f;
        const float repbox = (ab > 0) ? (float)(ar / (double)ab) : 0.0f;
        sScalar = sl1 + repgt + repbox;
    }
    __syncthreads();

    const float s = sScalar;
    float4* out4 = (float4*)out;
    out4[tid] = make_float4(s, s, s, s);            // 1024 float4 == 4096 floats
}

// ---------------------------------------------------------------------------
extern "C" void kernel_launch(void* const* d_in, const int* in_sizes, int n_in,
                              void* d_out, int out_size)
{
    const float* pred = (const float*)d_in[0];
    const float* tgt  = (const float*)d_in[1];
    float* out = (float*)d_out;

    rank_kernel<<<8, 1024>>>((const float4*)pred, (const float4*)tgt);
    scatter_kernel<<<8, 1024>>>((const float4*)pred, (const float4*)tgt);
    dim3 grid(32, 32);
    pair_kernel<<<grid, RPB>>>((const float4*)pred, (const float4*)tgt);
    final_kernel<<<1, 1024>>>(out);
}

// round 12
// speedup vs baseline: 1.3101x; 1.1863x over previous
#include <cuda_runtime.h>
#include <math.h>

#define NBOX   4096
#define RPB    128                      // pred rows per pair block
#define CHUNK  128                      // targets per pair block
#define NBLK   1024                     // 32x32 pair blocks
#define CBLK   32                       // combine blocks (x128 thr = NBOX)
#define NCELL  64                       // 8x8 spatial cells (100px), morton order

// Scratch (device globals: no allocation allowed in kernel_launch)
__device__ int    g_cnt[2 * NCELL];     // per-side per-cell counts (zeroed by combine)
__device__ float4 g_sP4[NBOX];          // spatially sorted preds
__device__ int    g_sPi[NBOX];          // original indices
__device__ float4 g_sT4[NBOX];          // spatially sorted targets
__device__ int    g_sTi[NBOX];
__device__ unsigned long long g_best[NBOX]; // packed (ratio_bits<<32 | ~argOrig); 0 = none
__device__ float  g_rbS[NBLK];
__device__ int    g_rbC[NBLK];
__device__ double g_pG[CBLK];           // combine-block RepGT sln partials
__device__ int    g_pC[CBLK];           // combine-block RepGT counts
__device__ double g_pL[CBLK];           // combine-block smooth-L1 partials
__device__ unsigned int g_ticket;       // combine last-block ticket

__device__ __forceinline__ int cellOf(float x, float y) {
    int cx = (int)(x * 0.01f); cx = cx < 0 ? 0 : (cx > 7 ? 7 : cx);
    int cy = (int)(y * 0.01f); cy = cy < 0 ? 0 : (cy > 7 ? 7 : cy);
    return (cx & 1) | ((cy & 1) << 1) | ((cx & 2) << 1) |
           ((cy & 2) << 2) | ((cx & 4) << 2) | ((cy & 4) << 3);
}

// ---------------------------------------------------------------------------
// Kernel 0: fused rank + scatter. 8 blocks x 1024, as TWO 4-CTA clusters
// (cluster == side: blocks 0-3 targets, 4-7 preds). The rank->scatter
// dependency is side-local, so a cluster barrier (~380 cyc) replaces R10's
// expensive global spin. v/cell/rank stay in registers across the barrier.
// ---------------------------------------------------------------------------
__global__ __launch_bounds__(1024) __cluster_dims__(4, 1, 1)
void sort_kernel(const float4* __restrict__ pred4,
                 const float4* __restrict__ tgt4)
{
    const int tid  = threadIdx.x;
    const int side = blockIdx.x >> 2;               // 0 = tgt, 1 = pred
    const int idx  = (blockIdx.x & 3) * 1024 + tid;
    const float4* src = side ? pred4 : tgt4;
    float4* dst  = side ? g_sP4 : g_sT4;
    int*    dsti = side ? g_sPi : g_sTi;

    if (blockIdx.x == 0 && tid == 0) g_ticket = 0u; // reset combine ticket

    __shared__ int sh[NCELL], sbase[NCELL], soff[NCELL];
    if (tid < NCELL) sh[tid] = 0;
    __syncthreads();

    const float4 v = src[idx];
    const int cell = cellOf(v.x, v.y);
    const int lr   = atomicAdd(&sh[cell], 1);
    __syncthreads();
    if (tid < NCELL) sbase[tid] = atomicAdd(&g_cnt[side * NCELL + tid], sh[tid]);
    __syncthreads();
    const int rank = sbase[cell] + lr;

    // ---- cluster barrier: all 4 blocks of this side have added their counts
    __threadfence();
    asm volatile("barrier.cluster.arrive.aligned;" ::: "memory");
    asm volatile("barrier.cluster.wait.aligned;" ::: "memory");

    if (tid == 0) {
        int acc = 0;
        for (int c = 0; c < NCELL; ++c) { soff[c] = acc; acc += g_cnt[side * NCELL + c]; }
    }
    __syncthreads();

    const int pos = soff[cell] + rank;
    dst[pos]  = v;
    dsti[pos] = idx;
}

// ---------------------------------------------------------------------------
// Kernel 1: pair sweep with block-level target compaction (R9-identical).
// ---------------------------------------------------------------------------
__global__ __launch_bounds__(RPB)
void pair_kernel()
{
    const int tid = threadIdx.x;
    const int bx = blockIdx.x, by = blockIdx.y;
    const int b  = bx * 32 + by;
    const int lane = tid & 31, wrp = tid >> 5;

    __shared__ float4 sT2[CHUNK];   // compacted targets {x0, y0, x2+1, y2+1}
    __shared__ float2 sAJ2[CHUNK];  // compacted (area+1conv, orig idx bits)
    __shared__ float4 sPB[4];       // per-warp pred bbox
    __shared__ int sCnt[4], sBase[4], sN;

    // --- own pred row + warp bbox ---
    const int r = bx * RPB + tid;
    float4 p = g_sP4[r];
    const int iO = g_sPi[r];
    const float areaP = (p.z - p.x + 1.0f) * (p.w - p.y + 1.0f);
    p.z += 1.0f; p.w += 1.0f;

    {
        float mnx = p.x, mxx = p.z, mny = p.y, mxy = p.w;
        #pragma unroll
        for (int o = 16; o > 0; o >>= 1) {
            mnx = fminf(mnx, __shfl_xor_sync(0xffffffffu, mnx, o));
            mxx = fmaxf(mxx, __shfl_xor_sync(0xffffffffu, mxx, o));
            mny = fminf(mny, __shfl_xor_sync(0xffffffffu, mny, o));
            mxy = fmaxf(mxy, __shfl_xor_sync(0xffffffffu, mxy, o));
        }
        if (lane == 0) sPB[wrp] = make_float4(mnx, mxx, mny, mxy);
    }
    __syncthreads();

    // block pred bbox (uniform)
    const float pmnx = fminf(fminf(sPB[0].x, sPB[1].x), fminf(sPB[2].x, sPB[3].x));
    const float pmxx = fmaxf(fmaxf(sPB[0].y, sPB[1].y), fmaxf(sPB[2].y, sPB[3].y));
    const float pmny = fminf(fminf(sPB[0].z, sPB[1].z), fminf(sPB[2].z, sPB[3].z));
    const float pmxy = fmaxf(fmaxf(sPB[0].w, sPB[1].w), fmaxf(sPB[2].w, sPB[3].w));

    // --- load my target, test vs block bbox, deterministic compaction ---
    {
        float4 t = g_sT4[by * CHUNK + tid];
        const int jO = g_sTi[by * CHUNK + tid];
        const float a = (t.z - t.x + 1.0f) * (t.w - t.y + 1.0f);
        t.z += 1.0f; t.w += 1.0f;
        const bool pass = (pmxx > t.x) && (t.z > pmnx) &&
                          (pmxy > t.y) && (t.w > pmny);
        const unsigned m = __ballot_sync(0xffffffffu, pass);
        if (lane == 0) sCnt[wrp] = __popc(m);
        __syncthreads();
        if (tid == 0) {
            int acc = 0;
            #pragma unroll
            for (int w = 0; w < 4; ++w) { sBase[w] = acc; acc += sCnt[w]; }
            sN = acc;
        }
        __syncthreads();
        if (pass) {
            const int pos = sBase[wrp] + __popc(m & ((1u << lane) - 1u));
            sT2[pos]  = t;
            sAJ2[pos] = make_float2(a, __int_as_float(jO));
        }
    }
    __syncthreads();

    const int nAct = sN;
    if (nAct == 0) {
        if (tid == 0) { g_rbS[b] = 0.0f; g_rbC[b] = 0; }
        return;
    }

    float bI = 0.0f, bU = 1.0f;
    int   bA = 0;
    float rbS = 0.0f;
    int   rbC = 0;

    #pragma unroll 4
    for (int k = 0; k < nAct; ++k) {
        const float4 t  = sT2[k];
        const float2 aj = sAJ2[k];
        float iw = fminf(p.z, t.z) - fmaxf(p.x, t.x);
        float ih = fminf(p.w, t.w) - fmaxf(p.y, t.y);
        iw = fmaxf(iw, 0.0f);
        ih = fmaxf(ih, 0.0f);
        const float inter = iw * ih;
        const float ua    = areaP + aj.x - inter;
        const int   jO    = __float_as_int(aj.y);
        if ((jO != iO) && (inter * bU > bI * ua)) {
            bI = inter; bU = ua; bA = jO;
        }
        if ((jO < iO) && (inter > 0.0f)) {
            rbS += __fdividef(inter, ua);
            rbC += 1;
        }
    }

    if (bI > 0.0f) {
        const float ratio = bI / bU;
        const unsigned long long packed =
            ((unsigned long long)__float_as_uint(ratio) << 32) |
            (unsigned long long)(0xFFFFFFFFu - (unsigned)bA);
        atomicMax(&g_best[iO], packed);    // indexed by ORIGINAL row
    }

    #pragma unroll
    for (int o = 16; o > 0; o >>= 1) {
        rbS += __shfl_down_sync(0xffffffffu, rbS, o);
        rbC += __shfl_down_sync(0xffffffffu, rbC, o);
    }
    __shared__ float wS[RPB / 32];
    __shared__ int   wC[RPB / 32];
    if (lane == 0) { wS[wrp] = rbS; wC[wrp] = rbC; }
    __syncthreads();
    if (tid == 0) {
        float s = 0.0f; int c = 0;
        #pragma unroll
        for (int w = 0; w < RPB / 32; ++w) { s += wS[w]; c += wC[w]; }
        g_rbS[b] = s;
        g_rbC[b] = c;
    }
}

// ---------------------------------------------------------------------------
// Kernel 2: combine + (last block) reduce + broadcast (R9-identical).
// Zeroes g_cnt / g_best for the next graph replay.
// ---------------------------------------------------------------------------
__global__ __launch_bounds__(128)
void combine_kernel(const float4* __restrict__ pred4,
                    const float4* __restrict__ tgt4,
                    float* __restrict__ out)
{
    const int tid = threadIdx.x;
    const int r   = blockIdx.x * 128 + tid;
    const int lane = tid & 31, wrp = tid >> 5;

    if (blockIdx.x == 0 && tid < 2 * NCELL) g_cnt[tid] = 0;   // reset for next replay

    const float4 pe = pred4[r];
    const float4 te = tgt4[r];
    float slf = 0.0f;
    {
        float d;
        d = fabsf(pe.x - te.x); slf += (d < 1.0f) ? 0.5f * d * d : d - 0.5f;
        d = fabsf(pe.y - te.y); slf += (d < 1.0f) ? 0.5f * d * d : d - 0.5f;
        d = fabsf(pe.z - te.z); slf += (d < 1.0f) ? 0.5f * d * d : d - 0.5f;
        d = fabsf(pe.w - te.w); slf += (d < 1.0f) ? 0.5f * d * d : d - 0.5f;
    }

    const unsigned long long packed = g_best[r];
    g_best[r] = 0ull;                       // reset for next replay

    float sgf = 0.0f;
    int   cgi = 0;
    if (packed != 0ull) {
        const int bA = (int)(0xFFFFFFFFu - (unsigned)(packed & 0xFFFFFFFFull));
        const float4 g = tgt4[bA];
        const float iw = fmaxf(fminf(pe.z, g.z) - fmaxf(pe.x, g.x), 0.0f);
        const float ih = fmaxf(fminf(pe.w, g.w) - fmaxf(pe.y, g.y), 0.0f);
        const float garea = (g.z - g.x) * (g.w - g.y);
        const float iog = iw * ih / garea;
        if (iog > 0.9f) {
            sgf = (iog - 0.9f) / (1.0f - 0.9f) + 2.3025851f;
        } else {
            const float xc = fminf(fmaxf(iog, 0.0f), 1.0f - 1e-6f);
            sgf = -log1pf(-xc);
        }
        cgi = 1;
    }

    double sg = (double)sgf, sl = (double)slf;
    int cg = cgi;
    #pragma unroll
    for (int o = 16; o > 0; o >>= 1) {
        sg += __shfl_down_sync(0xffffffffu, sg, o);
        sl += __shfl_down_sync(0xffffffffu, sl, o);
        cg += __shfl_down_sync(0xffffffffu, cg, o);
    }
    __shared__ double wG[4], wL[4];
    __shared__ int    wCt[4];
    if (lane == 0) { wG[wrp] = sg; wL[wrp] = sl; wCt[wrp] = cg; }
    __syncthreads();

    __shared__ unsigned int sIsLast;
    if (tid == 0) {
        double tg = 0.0, tl = 0.0; int tc = 0;
        #pragma unroll
        for (int w = 0; w < 4; ++w) { tg += wG[w]; tl += wL[w]; tc += wCt[w]; }
        g_pG[blockIdx.x] = tg;
        g_pL[blockIdx.x] = tl;
        g_pC[blockIdx.x] = tc;
        __threadfence();
        sIsLast = (atomicAdd(&g_ticket, 1u) == CBLK - 1u) ? 1u : 0u;
    }
    __syncthreads();
    if (sIsLast == 0u) return;

    double tsg = 0.0, tsl = 0.0, trb = 0.0;
    int tcg = 0; long long tcb = 0;
    if (tid < CBLK) {
        tsg = __ldcg(&g_pG[tid]);
        tsl = __ldcg(&g_pL[tid]);
        tcg = __ldcg(&g_pC[tid]);
    }
    #pragma unroll
    for (int q = 0; q < NBLK / 128; ++q) {
        const int bb = q * 128 + tid;
        trb += (double)__ldcg(&g_rbS[bb]);
        tcb += (long long)__ldcg(&g_rbC[bb]);
    }

    #pragma unroll
    for (int o = 16; o > 0; o >>= 1) {
        tsg += __shfl_down_sync(0xffffffffu, tsg, o);
        tsl += __shfl_down_sync(0xffffffffu, tsl, o);
        trb += __shfl_down_sync(0xffffffffu, trb, o);
        tcg += __shfl_down_sync(0xffffffffu, tcg, o);
        tcb += __shfl_down_sync(0xffffffffu, tcb, o);
    }
    __shared__ double fG[4], fL[4], fR[4];
    __shared__ int    fC[4];
    __shared__ long long fB[4];
    __shared__ float sScalar;
    if (lane == 0) { fG[wrp] = tsg; fL[wrp] = tsl; fR[wrp] = trb;
                     fC[wrp] = tcg; fB[wrp] = tcb; }
    __syncthreads();
    if (tid == 0) {
        double ag = 0.0, al = 0.0, ar = 0.0;
        int ac = 0; long long ab = 0;
        #pragma unroll
        for (int w = 0; w < 4; ++w) {
            ag += fG[w]; al += fL[w]; ar += fR[w]; ac += fC[w]; ab += fB[w];
        }
        const float sl1    = (float)(al / (double)(NBOX * 4));
        const float repgt  = (ac > 0) ? (float)(ag / (double)ac) : 0.0f;
        const float repbox = (ab > 0) ? (float)(ar / (double)ab) : 0.0f;
        sScalar = sl1 + repgt + repbox;
    }
    __syncthreads();

    const float s = sScalar;
    float4* out4 = (float4*)out;
    const float4 v = make_float4(s, s, s, s);
    #pragma unroll
    for (int q = tid; q < NBOX / 4; q += 128) out4[q] = v;
}

// ---------------------------------------------------------------------------
extern "C" void kernel_launch(void* const* d_in, const int* in_sizes, int n_in,
                              void* d_out, int out_size)
{
    const float* pred = (const float*)d_in[0];
    const float* tgt  = (const float*)d_in[1];
    float* out = (float*)d_out;

    sort_kernel<<<8, 1024>>>((const float4*)pred, (const float4*)tgt);
    dim3 grid(32, 32);
    pair_kernel<<<grid, RPB>>>();
    combine_kernel<<<CBLK, 128>>>((const float4*)pred, (const float4*)tgt, out);
}